// round 17
// baseline (speedup 1.0000x reference)
#include <cuda_runtime.h>
#include <cuda_bf16.h>
#include <cuda_fp16.h>
#include <cstdint>
#include <math.h>

// ---------------------------------------------------------------------------
// SwinTransformerLayer on GB300, mma.sync tensor cores.
// - QKV / proj / conv1x1 GEMMs: plain fp16 (residual-diluted error ~1e-4 each)
// - conv3x3: Winograd F(4x4,3x3); transform GEMMs bf16 3-term split, fp32 M
//   (16-bit anywhere in the winograd chain amplified ~6-10x — locked, R11).
// - fp16 trunk; half2 attention smem (R15); vectorized transforms (R16).
// Round 17: TM=128 / 3-CTA-per-SM GEMM variant for short-K QKV & proj
// (R16 profile: occ 23.7%, tensor 31% -> occupancy-limited latency).
// ---------------------------------------------------------------------------

#define BATCH   32
#define HH      56
#define WW_     56
#define CCH     192
#define WS      7
#define SHIFT   3
#define HEADS   6
#define HD      32
#define NTOK    49
#define MROWS   (BATCH*HH*WW_)   // 100352
#define HIDDEN  768
#define QKSCALE 0.17677669529663687f
#define NT4     6272             // 32 * 14 * 14 winograd F(4,3) tiles
#define NTP     6400             // padded to multiple of 256

#define TKB     32               // K elements per stage
#define ROWB    80               // padded row bytes (40 elems) — conflict-free ldmatrix

// ------------------------- scratch (device globals) ------------------------
__device__ __align__(16) __half        g_xw16 [(size_t)MROWS * CCH];
__device__ __align__(16) __half        g_qkv16[(size_t)MROWS * 3 * CCH];
__device__ __align__(16) __half        g_o16  [(size_t)MROWS * CCH];
__device__ __align__(16) __half        g_xmid [(size_t)MROWS * CCH];   // fp16 trunk
__device__ __align__(16) float         g_mu   [(size_t)MROWS];
__device__ __align__(16) float         g_rs   [(size_t)MROWS];
__device__ __align__(16) __half        g_h116 [(size_t)MROWS * HIDDEN];
// fp16 1-term weights, [N,K]
__device__ __align__(16) __half        g_wq16 [(size_t)576 * 192];
__device__ __align__(16) __half        g_wp16 [(size_t)192 * 192];
__device__ __align__(16) __half        g_w216 [(size_t)192 * 768];
// winograd F(4,3): 36 planes, bf16 3-term
__device__ __align__(16) __nv_bfloat16 g_U  [(size_t)36 * HIDDEN * 576];   // [p][co][3K]
__device__ __align__(16) __nv_bfloat16 g_Vh [(size_t)36 * NTP * CCH];
__device__ __align__(16) __nv_bfloat16 g_Vl [(size_t)36 * NTP * CCH];
__device__ __align__(16) float         g_M  [(size_t)36 * NTP * HIDDEN];   // fp32

// ------------------------------ PTX helpers --------------------------------
__device__ __forceinline__ void cp_async16(uint32_t dst, const void* src, bool full) {
    int sz = full ? 16 : 0;
    asm volatile("cp.async.cg.shared.global [%0], [%1], 16, %2;"
                 :: "r"(dst), "l"(src), "r"(sz) : "memory");
}
#define CP_COMMIT() asm volatile("cp.async.commit_group;" ::: "memory")
#define CP_WAIT(n)  asm volatile("cp.async.wait_group %0;" :: "n"(n) : "memory")

__device__ __forceinline__ void ldsm_x4(uint32_t addr, uint32_t r[4]) {
    asm volatile("ldmatrix.sync.aligned.m8n8.x4.shared.b16 {%0,%1,%2,%3}, [%4];"
                 : "=r"(r[0]), "=r"(r[1]), "=r"(r[2]), "=r"(r[3]) : "r"(addr));
}
template<typename T>
__device__ __forceinline__ void mma_any(float c[4], const uint32_t a[4],
                                        uint32_t b0, uint32_t b1);
template<>
__device__ __forceinline__ void mma_any<__nv_bfloat16>(float c[4], const uint32_t a[4],
                                                       uint32_t b0, uint32_t b1) {
    asm volatile("mma.sync.aligned.m16n8k16.row.col.f32.bf16.bf16.f32 "
                 "{%0,%1,%2,%3}, {%4,%5,%6,%7}, {%8,%9}, {%0,%1,%2,%3};"
                 : "+f"(c[0]), "+f"(c[1]), "+f"(c[2]), "+f"(c[3])
                 : "r"(a[0]), "r"(a[1]), "r"(a[2]), "r"(a[3]), "r"(b0), "r"(b1));
}
template<>
__device__ __forceinline__ void mma_any<__half>(float c[4], const uint32_t a[4],
                                                uint32_t b0, uint32_t b1) {
    asm volatile("mma.sync.aligned.m16n8k16.row.col.f32.f16.f16.f32 "
                 "{%0,%1,%2,%3}, {%4,%5,%6,%7}, {%8,%9}, {%0,%1,%2,%3};"
                 : "+f"(c[0]), "+f"(c[1]), "+f"(c[2]), "+f"(c[3])
                 : "r"(a[0]), "r"(a[1]), "r"(a[2]), "r"(a[3]), "r"(b0), "r"(b1));
}

__device__ __forceinline__ void split_bf16(float v, __nv_bfloat16& hi, __nv_bfloat16& lo) {
    hi = __float2bfloat16(v);
    lo = __float2bfloat16(v - __bfloat162float(hi));
}

__device__ __forceinline__ float2 f2add(float2 a, float2 b) { return make_float2(a.x + b.x, a.y + b.y); }
__device__ __forceinline__ float2 f2sub(float2 a, float2 b) { return make_float2(a.x - b.x, a.y - b.y); }
__device__ __forceinline__ float2 f2scl(float s, float2 a)  { return make_float2(s * a.x, s * a.y); }

// ----------------------------- weight prep ---------------------------------
#define NQ (192*576)
#define NP (192*192)
#define N2 (768*192)
__global__ void prep_all(const float* __restrict__ Wq, const float* __restrict__ Wp,
                         const float* __restrict__ W2,
                         __half* __restrict__ Dq, __half* __restrict__ Dp,
                         __half* __restrict__ D2)
{
    int i = blockIdx.x * 256 + threadIdx.x;
    if (i < NQ) {
        int k = i / 576, n = i % 576;
        Dq[(size_t)n * 192 + k] = __float2half(Wq[i]);
    } else if (i < NQ + NP) {
        int j = i - NQ;
        int k = j / 192, n = j % 192;
        Dp[(size_t)n * 192 + k] = __float2half(Wp[j]);
    } else if (i < NQ + NP + N2) {
        int j = i - NQ - NP;
        int k = j / 192, n = j % 192;
        D2[(size_t)n * 768 + k] = __float2half(W2[j]);
    }
}

// ----------------------- winograd weight transform --------------------------
__global__ void wino_wt(const float* __restrict__ W, __nv_bfloat16* __restrict__ U)
{
    int i = blockIdx.x * 256 + threadIdx.x;
    if (i >= CCH * HIDDEN) return;
    int ci = i % CCH, co = i / CCH;

    float g[3][3];
    #pragma unroll
    for (int ky = 0; ky < 3; ky++)
        #pragma unroll
        for (int kx = 0; kx < 3; kx++)
            g[ky][kx] = W[((size_t)(ky * 3 + kx) * CCH + ci) * HIDDEN + co];

    float u[6][3];
    #pragma unroll
    for (int c = 0; c < 3; c++) {
        float g0 = g[0][c], g1 = g[1][c], g2 = g[2][c];
        u[0][c] = 0.25f * g0;
        u[1][c] = -(g0 + g1 + g2) * (1.0f / 6.0f);
        u[2][c] = (-g0 + g1 - g2) * (1.0f / 6.0f);
        u[3][c] = g0 * (1.0f / 24.0f) + g1 * (1.0f / 12.0f) + g2 * (1.0f / 6.0f);
        u[4][c] = g0 * (1.0f / 24.0f) - g1 * (1.0f / 12.0f) + g2 * (1.0f / 6.0f);
        u[5][c] = g2;
    }
    #pragma unroll
    for (int r = 0; r < 6; r++) {
        float a0 = u[r][0], a1 = u[r][1], a2 = u[r][2];
        float U6[6];
        U6[0] = 0.25f * a0;
        U6[1] = -(a0 + a1 + a2) * (1.0f / 6.0f);
        U6[2] = (-a0 + a1 - a2) * (1.0f / 6.0f);
        U6[3] = a0 * (1.0f / 24.0f) + a1 * (1.0f / 12.0f) + a2 * (1.0f / 6.0f);
        U6[4] = a0 * (1.0f / 24.0f) - a1 * (1.0f / 12.0f) + a2 * (1.0f / 6.0f);
        U6[5] = a2;
        #pragma unroll
        for (int c = 0; c < 6; c++) {
            int p = r * 6 + c;
            __nv_bfloat16 hi, lo;
            split_bf16(U6[c], hi, lo);
            size_t base = ((size_t)p * HIDDEN + co) * 576;
            U[base + ci]       = hi;
            U[base + 192 + ci] = hi;
            U[base + 384 + ci] = lo;
        }
    }
}

// ------------------------ LN row statistics (for LN2) -----------------------
__global__ __launch_bounds__(256)
void ln_stats(const __half* __restrict__ x, float* __restrict__ mu_o,
              float* __restrict__ rs_o)
{
    int m = blockIdx.x * 8 + (threadIdx.x >> 5);
    int lane = threadIdx.x & 31;
    const __half2* src = reinterpret_cast<const __half2*>(x + (size_t)m * CCH);
    float s1 = 0.f, s2 = 0.f;
    #pragma unroll
    for (int q = 0; q < 3; q++) {
        float2 v = __half22float2(src[lane + 32 * q]);
        s1 += v.x + v.y; s2 += v.x * v.x + v.y * v.y;
    }
    #pragma unroll
    for (int o = 16; o > 0; o >>= 1) {
        s1 += __shfl_xor_sync(0xFFFFFFFF, s1, o);
        s2 += __shfl_xor_sync(0xFFFFFFFF, s2, o);
    }
    if (lane == 0) {
        float mu  = s1 * (1.0f / CCH);
        float var = s2 * (1.0f / CCH) - mu * mu;
        mu_o[m] = mu;
        rs_o[m] = rsqrtf(var + 1e-3f);
    }
}

// ----------------- winograd input transform (LN2 fused) ---------------------
__device__ __forceinline__ void bt6_2(const float2 d[6], float2 t[6]) {
    t[0] = f2add(f2sub(f2scl(4.f, d[0]), f2scl(5.f, d[2])), d[4]);
    t[1] = f2add(f2add(f2sub(f2scl(-4.f, d[1]), f2scl(4.f, d[2])), d[3]), d[4]);
    t[2] = f2add(f2sub(f2sub(f2scl(4.f, d[1]), f2scl(4.f, d[2])), d[3]), d[4]);
    t[3] = f2add(f2add(f2sub(f2scl(-2.f, d[1]), d[2]), f2scl(2.f, d[3])), d[4]);
    t[4] = f2add(f2sub(f2sub(f2scl(2.f, d[1]), d[2]), f2scl(2.f, d[3])), d[4]);
    t[5] = f2add(f2sub(f2scl(4.f, d[1]), f2scl(5.f, d[3])), d[5]);
}

__global__ __launch_bounds__(256)
void wino_in(const __half* __restrict__ x,
             const float* __restrict__ mu,
             const float* __restrict__ rs,
             const float* __restrict__ gamma,
             const float* __restrict__ beta,
             __nv_bfloat16* __restrict__ Vh,
             __nv_bfloat16* __restrict__ Vl)
{
    int i = blockIdx.x * 256 + threadIdx.x;
    if (i >= NT4 * (CCH / 2)) return;
    int tile = i / (CCH / 2), cp = i % (CCH / 2);
    int b = tile / 196, r = tile % 196, ty = r / 14, tx = r % 14;
    float2 gm = *reinterpret_cast<const float2*>(gamma + 2 * cp);
    float2 bt = *reinterpret_cast<const float2*>(beta + 2 * cp);

    float2 d[6][6];
    #pragma unroll
    for (int ii = 0; ii < 6; ii++) {
        int h = 4 * ty - 1 + ii;
        #pragma unroll
        for (int jj = 0; jj < 6; jj++) {
            int w = 4 * tx - 1 + jj;
            bool ok = (h >= 0) && (h < HH) && (w >= 0) && (w < WW_);
            if (ok) {
                size_t row = (size_t)(b * HH + h) * WW_ + w;
                float2 v = __half22float2(
                    *reinterpret_cast<const __half2*>(x + row * CCH + 2 * cp));
                float mr = mu[row], rr2 = rs[row];
                d[ii][jj].x = (v.x - mr) * rr2 * gm.x + bt.x;
                d[ii][jj].y = (v.y - mr) * rr2 * gm.y + bt.y;
            } else d[ii][jj] = make_float2(0.f, 0.f);
        }
    }
    #pragma unroll
    for (int jj = 0; jj < 6; jj++) {
        float2 col[6], tc[6];
        #pragma unroll
        for (int ii = 0; ii < 6; ii++) col[ii] = d[ii][jj];
        bt6_2(col, tc);
        #pragma unroll
        for (int ii = 0; ii < 6; ii++) d[ii][jj] = tc[ii];
    }
    #pragma unroll
    for (int ii = 0; ii < 6; ii++) {
        float2 V6[6];
        bt6_2(d[ii], V6);
        #pragma unroll
        for (int jj = 0; jj < 6; jj++) {
            int p = ii * 6 + jj;
            __nv_bfloat16 hx, lx, hy, ly;
            split_bf16(V6[jj].x, hx, lx);
            split_bf16(V6[jj].y, hy, ly);
            size_t idx = ((size_t)p * NTP + tile) * CCH + 2 * cp;
            __nv_bfloat162 hv; hv.x = hx; hv.y = hy;
            __nv_bfloat162 lv; lv.x = lx; lv.y = ly;
            *reinterpret_cast<__nv_bfloat162*>(Vh + idx) = hv;
            *reinterpret_cast<__nv_bfloat162*>(Vl + idx) = lv;
        }
    }
}

// ----------------------- winograd output transform --------------------------
__device__ __forceinline__ void at6_2(const float2 m[6], float2 s[4]) {
    s[0] = f2add(f2add(f2add(f2add(m[0], m[1]), m[2]), m[3]), m[4]);
    s[1] = f2sub(f2add(f2sub(m[1], m[2]), f2scl(2.f, m[3])), f2scl(2.f, m[4]));
    s[2] = f2add(f2add(f2add(m[1], m[2]), f2scl(4.f, m[3])), f2scl(4.f, m[4]));
    s[3] = f2add(f2add(f2sub(f2sub(m[1], m[2]), f2scl(8.f, m[4])), f2scl(8.f, m[3])), m[5]);
}

__global__ __launch_bounds__(256)
void wino_out(const float* __restrict__ M,
              const float* __restrict__ scale,
              const float* __restrict__ shiftv,
              __half* __restrict__ h116)
{
    int i = blockIdx.x * 256 + threadIdx.x;
    if (i >= NT4 * (HIDDEN / 2)) return;
    int tile = i / (HIDDEN / 2), cop = i % (HIDDEN / 2);
    int b = tile / 196, r = tile % 196, ty = r / 14, tx = r % 14;

    float2 m[6][6];
    #pragma unroll
    for (int p = 0; p < 36; p++)
        m[p / 6][p % 6] = *reinterpret_cast<const float2*>(
            M + ((size_t)p * NTP + tile) * HIDDEN + 2 * cop);

    float2 s[4][6];
    #pragma unroll
    for (int jj = 0; jj < 6; jj++) {
        float2 col[6], sc4[4];
        #pragma unroll
        for (int ii = 0; ii < 6; ii++) col[ii] = m[ii][jj];
        at6_2(col, sc4);
        #pragma unroll
        for (int ii = 0; ii < 4; ii++) s[ii][jj] = sc4[ii];
    }
    float2 sc = *reinterpret_cast<const float2*>(scale + 2 * cop);
    float2 sh = *reinterpret_cast<const float2*>(shiftv + 2 * cop);
    #pragma unroll
    for (int ii = 0; ii < 4; ii++) {
        float2 Y4[4];
        at6_2(s[ii], Y4);
        #pragma unroll
        for (int jj = 0; jj < 4; jj++) {
            float vx = Y4[jj].x * sc.x + sh.x;
            float vy = Y4[jj].y * sc.y + sh.y;
            vx = 0.5f * vx * (1.0f + erff(vx * 0.70710678118654752f));
            vy = 0.5f * vy * (1.0f + erff(vy * 0.70710678118654752f));
            size_t px = (size_t)b * 3136 + (size_t)(4 * ty + ii) * 56 + (4 * tx + jj);
            *reinterpret_cast<__half2*>(h116 + px * HIDDEN + 2 * cop) =
                __floats2half2_rn(vx, vy);
        }
    }
}

// ------------------------------- LayerNorm (LN1) ----------------------------
__global__ __launch_bounds__(256)
void ln_kernel(const float* __restrict__ x,
               const float* __restrict__ gamma,
               const float* __restrict__ beta,
               __half* __restrict__ out16)
{
    int m = blockIdx.x * 8 + (threadIdx.x >> 5);
    int lane = threadIdx.x & 31;

    int win = m / NTOK, tok = m % NTOK;
    int b  = win >> 6, wi = win & 63;
    int hs = (wi >> 3) * WS + tok / WS;
    int ws = (wi & 7)  * WS + tok % WS;
    int h = hs + SHIFT; if (h >= HH)  h -= HH;
    int w = ws + SHIFT; if (w >= WW_) w -= WW_;
    int src_p = (b * HH + h) * WW_ + w;

    const float2* src = reinterpret_cast<const float2*>(x + (size_t)src_p * CCH);
    float2 v[3];
    float s1 = 0.f, s2 = 0.f;
    #pragma unroll
    for (int q = 0; q < 3; q++) {
        v[q] = src[lane + 32 * q];
        s1 += v[q].x + v[q].y;
        s2 += v[q].x * v[q].x + v[q].y * v[q].y;
    }
    #pragma unroll
    for (int o = 16; o > 0; o >>= 1) {
        s1 += __shfl_xor_sync(0xFFFFFFFF, s1, o);
        s2 += __shfl_xor_sync(0xFFFFFFFF, s2, o);
    }
    float mu  = s1 * (1.0f / CCH);
    float var = s2 * (1.0f / CCH) - mu * mu;
    float rsg = rsqrtf(var + 1e-3f);

    #pragma unroll
    for (int q = 0; q < 3; q++) {
        int cp = lane + 32 * q;
        float2 gm = *reinterpret_cast<const float2*>(gamma + 2 * cp);
        float2 bt = *reinterpret_cast<const float2*>(beta + 2 * cp);
        float yx = (v[q].x - mu) * rsg * gm.x + bt.x;
        float yy = (v[q].y - mu) * rsg * gm.y + bt.y;
        *reinterpret_cast<__half2*>(out16 + (size_t)m * CCH + 2 * cp) =
            __floats2half2_rn(yx, yy);
    }
}

// ------------------------------- Attention ---------------------------------
#define QKP2 17
__global__ void attn_kernel(const __half* __restrict__ qkv,
                            const float* __restrict__ table,
                            __half* __restrict__ o16)
{
    int blk = blockIdx.x;
    int win = blk / HEADS;
    int head = blk % HEADS;
    int tid = threadIdx.x;

    __shared__ __half2 qs2[NTOK * QKP2], ks2[NTOK * QKP2], vs2[NTOK * 16];
    __shared__ float S[NTOK * 50];

    const __half2 scale2 = __floats2half2_rn(QKSCALE, QKSCALE);
    for (int t = tid; t < NTOK * 16; t += 128) {
        int n = t >> 4, dp = t & 15;
        const __half2* base = reinterpret_cast<const __half2*>(
            qkv + (size_t)(win * NTOK + n) * (3 * CCH) + head * HD) + dp;
        qs2[n * QKP2 + dp] = __hmul2(base[0], scale2);
        ks2[n * QKP2 + dp] = base[CCH / 2];
        vs2[t] = base[CCH];
    }
    __syncthreads();

    int wi = win & 63;
    int wh = wi >> 3, wwn = wi & 7;

    for (int t = tid; t < NTOK * NTOK; t += 128) {
        int n = t / NTOK, mm = t % NTOK;
        float s = 0.f;
        #pragma unroll
        for (int dp = 0; dp < 16; dp++) {
            float2 a = __half22float2(qs2[n * QKP2 + dp]);
            float2 b = __half22float2(ks2[mm * QKP2 + dp]);
            s += a.x * b.x + a.y * b.y;
        }
        int rn = n / WS, cn = n % WS, rm = mm / WS, cm = mm % WS;
        int idx = (rn - rm + WS - 1) * (2 * WS - 1) + (cn - cm + WS - 1);
        s += table[idx * HEADS + head];
        int hn = wh * WS + rn, wn = wwn * WS + cn;
        int hm = wh * WS + rm, wm = wwn * WS + cm;
        int reg_n = (hn < 49 ? 0 : (hn < 53 ? 1 : 2)) * 3 + (wn < 49 ? 0 : (wn < 53 ? 1 : 2));
        int reg_m = (hm < 49 ? 0 : (hm < 53 ? 1 : 2)) * 3 + (wm < 49 ? 0 : (wm < 53 ? 1 : 2));
        if (reg_n != reg_m) s -= 100.0f;
        S[n * 50 + mm] = s;
    }
    __syncthreads();

    // warp-per-row softmax
    {
        int w4 = tid >> 5, lane = tid & 31;
        for (int row = w4; row < NTOK; row += 4) {
            float* Sr = S + row * 50;
            float mx = -1e30f;
            for (int c = lane; c < NTOK; c += 32) mx = fmaxf(mx, Sr[c]);
            #pragma unroll
            for (int o = 16; o > 0; o >>= 1)
                mx = fmaxf(mx, __shfl_xor_sync(0xFFFFFFFF, mx, o));
            float sum = 0.f;
            for (int c = lane; c < NTOK; c += 32) {
                float e = __expf(Sr[c] - mx);
                Sr[c] = e; sum += e;
            }
            #pragma unroll
            for (int o = 16; o > 0; o >>= 1)
                sum += __shfl_xor_sync(0xFFFFFFFF, sum, o);
            float inv = 1.0f / sum;
            for (int c = lane; c < NTOK; c += 32) Sr[c] *= inv;
        }
    }
    __syncthreads();

    for (int t = tid; t < NTOK * 16; t += 128) {
        int n = t >> 4, dp = t & 15;
        float2 acc = make_float2(0.f, 0.f);
        #pragma unroll 7
        for (int m2 = 0; m2 < NTOK; m2++) {
            float p = S[n * 50 + m2];
            float2 v = __half22float2(vs2[m2 * 16 + dp]);
            acc.x += p * v.x;
            acc.y += p * v.y;
        }
        size_t idx = (size_t)(win * NTOK + n) * CCH + head * HD + 2 * dp;
        *reinterpret_cast<__half2*>(o16 + idx) = __floats2half2_rn(acc.x, acc.y);
    }
}

// ---------------------------- HMMA GEMM ------------------------------------
// Warp grid 4xWM rows x 2xWN cols; TM = 4*WM.  WM=64: 2 CTA/SM (big tiles).
// WM=32: 3 CTA/SM (occupancy for short-K latency-bound GEMMs).
// SPLIT=1 (fp16) plain; SPLIT=3 (bf16) 3-term [Ah|Al|Ah].
// epi: 2=+bias,remap,+addF(f32) -> f16   4=BN,+addH(f16) -> f32
//      5=raw -> f32                       6=+bias -> f16
template<int WM, int WN, int MINCTA, int SPLIT, int STG, typename T>
__global__ __launch_bounds__(256, MINCTA)
void gemm_tc(const T* __restrict__ Ah,
             const T* __restrict__ Al,
             const T* __restrict__ Bs,
             const float* __restrict__ bias,
             float* __restrict__ Cf,
             __half* __restrict__ C16,
             const float* __restrict__ scale,
             const float* __restrict__ shiftv,
             const float* __restrict__ addF,
             const __half* __restrict__ addH,
             int N, int K1, int epi,
             size_t zsA, size_t zsB, size_t zsC)
{
    constexpr int TMX  = 4 * WM;
    constexpr int MI   = WM / 16;        // m-fragments per warp
    constexpr int NB   = WN / 16;        // B ldsm per ks
    constexpr int NI   = WN / 8;         // n-fragments per warp
    constexpr int TN   = 2 * WN;
    constexpr int A_STGB = TMX * ROWB;
    constexpr int B_STGB = TN * ROWB;
    constexpr int ALOAD = TMX / 64;      // A load passes
    constexpr int BPASS = TN / 64;       // B load passes

    Ah += blockIdx.z * zsA;
    Al += blockIdx.z * zsA;
    Bs += blockIdx.z * zsB;
    if (Cf) Cf += blockIdx.z * zsC;

    extern __shared__ char smem[];
    uint32_t sA0 = (uint32_t)__cvta_generic_to_shared(smem);
    uint32_t sB0 = sA0 + STG * A_STGB;

    int tid = threadIdx.x;
    int wid = tid >> 5, lid = tid & 31;
    int wr = wid >> 1, wc = wid & 1;
    int m0 = blockIdx.y * TMX, n0 = blockIdx.x * TN;
    int KS = SPLIT * K1;
    int nk = KS / TKB;

    int arow = tid >> 2;
    int aj = tid & 3;
    size_t arowoff[ALOAD];
    #pragma unroll
    for (int p = 0; p < ALOAD; p++) arowoff[p] = (size_t)(m0 + arow + p * 64) * K1;
    size_t browoff[BPASS];
    #pragma unroll
    for (int p = 0; p < BPASS; p++)
        browoff[p] = (size_t)(n0 + arow + p * 64) * KS;

    float acc[MI][NI][4];
    #pragma unroll
    for (int i = 0; i < MI; i++)
        #pragma unroll
        for (int j = 0; j < NI; j++)
            #pragma unroll
            for (int q = 0; q < 4; q++) acc[i][j][q] = 0.f;

    auto load_stage = [&](int kt) {
        int s = kt % STG;
        int k3 = kt * TKB;
        int seg = k3 / K1;
        int kk = k3 - seg * K1;
        const T* Asrc = (SPLIT == 3 && seg == 1) ? Al : Ah;
        #pragma unroll
        for (int p = 0; p < ALOAD; p++) {
            uint32_t dst = sA0 + s * A_STGB + (arow + p * 64) * ROWB + aj * 16;
            cp_async16(dst, Asrc + arowoff[p] + kk + aj * 8, true);
        }
        #pragma unroll
        for (int p = 0; p < BPASS; p++) {
            uint32_t dst = sB0 + s * B_STGB + (arow + p * 64) * ROWB + aj * 16;
            cp_async16(dst, Bs + browoff[p] + k3 + aj * 8, true);
        }
    };

    auto compute = [&](int s) {
        uint32_t aBase = sA0 + s * A_STGB + (wr * WM + (lid & 15)) * ROWB + (lid >> 4) * 16;
        uint32_t bBase = sB0 + s * B_STGB
                       + (wc * WN + (lid & 7) + ((lid >> 4) << 3)) * ROWB
                       + ((lid >> 3) & 1) * 16;
        #pragma unroll
        for (int ks = 0; ks < 2; ks++) {
            uint32_t a[MI][4], b[NB][4];
            #pragma unroll
            for (int mi = 0; mi < MI; mi++)
                ldsm_x4(aBase + mi * 16 * ROWB + ks * 32, a[mi]);
            #pragma unroll
            for (int bi = 0; bi < NB; bi++)
                ldsm_x4(bBase + bi * 16 * ROWB + ks * 32, b[bi]);
            #pragma unroll
            for (int mi = 0; mi < MI; mi++)
                #pragma unroll
                for (int ni = 0; ni < NI; ni++)
                    mma_any<T>(acc[mi][ni], a[mi],
                               b[ni >> 1][(ni & 1) * 2], b[ni >> 1][(ni & 1) * 2 + 1]);
        }
    };

    #pragma unroll
    for (int p = 0; p < STG - 1; p++) { if (p < nk) load_stage(p); CP_COMMIT(); }

    for (int kt = 0; kt < nk; kt++) {
        CP_WAIT(STG - 2);
        __syncthreads();
        if (kt + STG - 1 < nk) load_stage(kt + STG - 1);
        CP_COMMIT();
        compute(kt % STG);
    }

    // ------------------------------ epilogue -------------------------------
    int g = lid >> 2, t2 = (lid & 3) * 2;
    #pragma unroll
    for (int mi = 0; mi < MI; mi++) {
        #pragma unroll
        for (int rr = 0; rr < 2; rr++) {
            int m = m0 + wr * WM + mi * 16 + g + rr * 8;
            size_t orow;
            if (epi == 2) {
                int win = m / NTOK, tok = m % NTOK;
                int b = win >> 6, wi2 = win & 63;
                int hs = (wi2 >> 3) * WS + tok / WS;
                int ws = (wi2 & 7)  * WS + tok % WS;
                int h = hs + SHIFT; if (h >= HH)  h -= HH;
                int w = ws + SHIFT; if (w >= WW_) w -= WW_;
                orow = (size_t)(b * HH + h) * WW_ + w;
            } else {
                orow = (size_t)m;
            }
            #pragma unroll
            for (int ni = 0; ni < NI; ni++) {
                int n = n0 + wc * WN + ni * 8 + t2;
                float v0 = acc[mi][ni][rr * 2 + 0];
                float v1 = acc[mi][ni][rr * 2 + 1];
                if (epi == 6) {
                    __half2 o;
                    o.x = __float2half(v0 + bias[n]);
                    o.y = __float2half(v1 + bias[n + 1]);
                    *reinterpret_cast<__half2*>(C16 + (size_t)m * N + n) = o;
                } else if (epi == 2) {
                    size_t oi = orow * CCH + n;
                    float2 a4 = *reinterpret_cast<const float2*>(addF + oi);
                    __half2 o;
                    o.x = __float2half(v0 + bias[n] + a4.x);
                    o.y = __float2half(v1 + bias[n + 1] + a4.y);
                    *reinterpret_cast<__half2*>(C16 + oi) = o;
                } else if (epi == 4) {
                    size_t oi = (size_t)m * CCH + n;
                    float2 a4 = __half22float2(
                        *reinterpret_cast<const __half2*>(addH + oi));
                    float2 o = { v0 * scale[n] + shiftv[n] + a4.x,
                                 v1 * scale[n + 1] + shiftv[n + 1] + a4.y };
                    *reinterpret_cast<float2*>(Cf + oi) = o;
                } else {  // epi == 5: raw fp32
                    float2 o = { v0, v1 };
                    *reinterpret_cast<float2*>(Cf + (size_t)m * N + n) = o;
                }
            }
        }
    }
}

// ------------------------------- launcher -----------------------------------
extern "C" void kernel_launch(void* const* d_in, const int* in_sizes, int n_in,
                              void* d_out, int out_size)
{
    const float* x         = (const float*)d_in[0];
    const float* ln1_g     = (const float*)d_in[1];
    const float* ln1_b     = (const float*)d_in[2];
    const float* w_qkv     = (const float*)d_in[3];
    const float* b_qkv     = (const float*)d_in[4];
    const float* bias_tbl  = (const float*)d_in[5];
    const float* w_proj    = (const float*)d_in[6];
    const float* b_proj    = (const float*)d_in[7];
    const float* ln2_g     = (const float*)d_in[8];
    const float* ln2_b     = (const float*)d_in[9];
    const float* w_ffn1    = (const float*)d_in[10];
    const float* bn1_scale = (const float*)d_in[11];
    const float* bn1_shift = (const float*)d_in[12];
    const float* w_ffn2    = (const float*)d_in[13];
    const float* bn2_scale = (const float*)d_in[14];
    const float* bn2_shift = (const float*)d_in[15];
    float* out = (float*)d_out;

    __half *xw16, *qkv16, *o16, *xmid16, *h116, *wq16, *wp16, *w216;
    __nv_bfloat16 *U, *Vh, *Vl;
    float *mu, *rs, *Mbuf;
    cudaGetSymbolAddress((void**)&xw16,   g_xw16);
    cudaGetSymbolAddress((void**)&qkv16,  g_qkv16);
    cudaGetSymbolAddress((void**)&o16,    g_o16);
    cudaGetSymbolAddress((void**)&xmid16, g_xmid);
    cudaGetSymbolAddress((void**)&mu,     g_mu);
    cudaGetSymbolAddress((void**)&rs,     g_rs);
    cudaGetSymbolAddress((void**)&h116,   g_h116);
    cudaGetSymbolAddress((void**)&wq16,   g_wq16);
    cudaGetSymbolAddress((void**)&wp16,   g_wp16);
    cudaGetSymbolAddress((void**)&w216,   g_w216);
    cudaGetSymbolAddress((void**)&U,  g_U);
    cudaGetSymbolAddress((void**)&Vh, g_Vh); cudaGetSymbolAddress((void**)&Vl, g_Vl);
    cudaGetSymbolAddress((void**)&Mbuf, g_M);

    constexpr int SM3_128 = 3 * (128 * ROWB + 64 * ROWB);  // 46080 (TM=128)
    constexpr int SM4_256 = 4 * (256 * ROWB + 64 * ROWB);  // 102400 (TM=256)
    cudaFuncSetAttribute((const void*)gemm_tc<32,32,3,1,3,__half>,
                         cudaFuncAttributeMaxDynamicSharedMemorySize, SM3_128);
    cudaFuncSetAttribute((const void*)gemm_tc<64,32,2,1,4,__half>,
                         cudaFuncAttributeMaxDynamicSharedMemorySize, SM4_256);
    cudaFuncSetAttribute((const void*)gemm_tc<64,32,2,3,4,__nv_bfloat16>,
                         cudaFuncAttributeMaxDynamicSharedMemorySize, SM4_256);

    // weight preps
    prep_all<<<(NQ + NP + N2 + 255) / 256, 256>>>(w_qkv, w_proj, w_ffn2,
                                                  wq16, wp16, w216);
    wino_wt<<<(CCH * HIDDEN + 255) / 256, 256>>>(w_ffn1, U);

    // LN1 + roll + window partition -> fp16
    ln_kernel<<<MROWS / 8, 256>>>(x, ln1_g, ln1_b, xw16);

    // QKV GEMM [M,192]x[192,576] fp16 -> fp16  (TM=128, 3 CTA/SM)
    gemm_tc<32,32,3,1,3,__half><<<dim3(576 / 64, MROWS / 128), 256, SM3_128>>>(
        xw16, xw16, wq16, b_qkv, nullptr, qkv16, nullptr, nullptr, nullptr, nullptr,
        576, 192, 6, 0, 0, 0);

    // attention -> fp16
    attn_kernel<<<(MROWS / NTOK) * HEADS, 128>>>(qkv16, bias_tbl, o16);

    // proj GEMM + window reverse + roll + shortcut(x fp32) -> fp16 trunk (TM=128)
    gemm_tc<32,32,3,1,3,__half><<<dim3(192 / 64, MROWS / 128), 256, SM3_128>>>(
        o16, o16, wp16, b_proj, nullptr, xmid16, nullptr, nullptr, x, nullptr,
        192, 192, 2, 0, 0, 0);

    // LN2 row stats (fp16 trunk)
    ln_stats<<<MROWS / 8, 256>>>(xmid16, mu, rs);

    // winograd F(4,3) input transform with fused LN2 -> bf16 hi/lo (2 ch/thread)
    wino_in<<<(NT4 * (CCH / 2) + 255) / 256, 256>>>(xmid16, mu, rs, ln2_g, ln2_b, Vh, Vl);

    // 36 batched transform GEMMs [6400,192]x[192,768] -> fp32 M (TM=256, STAGES=4)
    gemm_tc<64,32,2,3,4,__nv_bfloat16><<<dim3(HIDDEN / 64, NTP / 256, 36), 256, SM4_256>>>(
        Vh, Vl, U, nullptr, Mbuf, nullptr, nullptr, nullptr, nullptr, nullptr,
        HIDDEN, 192, 5,
        (size_t)NTP * CCH, (size_t)HIDDEN * 576, (size_t)NTP * HIDDEN);

    // winograd output transform + BN + GELU -> h1 fp16 (2 ch/thread)
    wino_out<<<(NT4 * (HIDDEN / 2) + 255) / 256, 256>>>(Mbuf, bn1_scale, bn1_shift, h116);

    // conv1x1 GEMM + BN + residual(fp16 trunk) -> out fp32 (TM=256, STAGES=4)
    gemm_tc<64,32,2,1,4,__half><<<dim3(CCH / 64, MROWS / 256), 256, SM4_256>>>(
        h116, h116, w216, nullptr, out, nullptr, bn2_scale, bn2_shift, nullptr, xmid16,
        CCH, 768, 4, 0, 0, 0);
}